// round 12
// baseline (speedup 1.0000x reference)
#include <cuda_runtime.h>

#define CONCEPTS 128
#define MM 14          // nb_mod_max + 2
#define DC 128         // concept dim
#define DIN 3

// Per-concept Gram G = W[c] W[c]^T, padded to 8 floats: {G00,G01,G02,G11,G12,G22,_,_}
__device__ float g_G[CONCEPTS * 8];

__device__ __forceinline__ unsigned redux_min_u32(unsigned v, unsigned mask) {
    unsigned r;
    asm volatile("redux.sync.min.u32 %0, %1, %2;" : "=r"(r) : "r"(v), "r"(mask));
    return r;
}

// ---------------------------------------------------------------------------
// G[c] = W[c] W[c]^T. One warp per concept.
// ---------------------------------------------------------------------------
__global__ void gmat_kernel(const float* __restrict__ W) {
    int c = blockIdx.x;
    int lane = threadIdx.x;
    const float4* w = reinterpret_cast<const float4*>(W + (size_t)c * DIN * DC);
    float4 a = w[lane];
    float4 b = w[32 + lane];
    float4 d = w[64 + lane];
    float s[6];
    s[0] = a.x*a.x + a.y*a.y + a.z*a.z + a.w*a.w;
    s[1] = a.x*b.x + a.y*b.y + a.z*b.z + a.w*b.w;
    s[2] = a.x*d.x + a.y*d.y + a.z*d.z + a.w*d.w;
    s[3] = b.x*b.x + b.y*b.y + b.z*b.z + b.w*b.w;
    s[4] = b.x*d.x + b.y*d.y + b.z*d.z + b.w*d.w;
    s[5] = d.x*d.x + d.y*d.y + d.z*d.z + d.w*d.w;
    #pragma unroll
    for (int off = 16; off; off >>= 1)
        #pragma unroll
        for (int k = 0; k < 6; k++)
            s[k] += __shfl_xor_sync(0xffffffffu, s[k], off);
    if (lane == 0) {
        #pragma unroll
        for (int k = 0; k < 6; k++) g_G[c * 8 + k] = s[k];
        g_G[c * 8 + 6] = 0.0f;
        g_G[c * 8 + 7] = 0.0f;
    }
}

// ---------------------------------------------------------------------------
// 4 rows per warp; 8 lanes per row (grp = lane>>3, sub = lane&7).
// Per LDG.128: 4 rows x 128B contiguous = 4 full lines (wavefront-optimal).
// __launch_bounds__(256, 8) caps regs at 32 -> up to 64 resident warps/SM:
// the kernel is latency-bound on L2 gathers, so warp count is the limiter.
// ---------------------------------------------------------------------------
__global__ void __launch_bounds__(256, 8) impact_kernel(
    const int*   __restrict__ user_ids,
    const int*   __restrict__ item_ids,
    const int*   __restrict__ concept_ids,
    const float* __restrict__ uemb,     // (USER_N, 128)
    const float* __restrict__ irw,      // (ITEM_N*14, 3)
    const float* __restrict__ W,        // (128, 3, 128)
    const float* __restrict__ maskt,    // (ITEM_N, 14)  [unused — derived from nbmod]
    const int*   __restrict__ nbmod,    // (ITEM_N,)
    float*       __restrict__ out,
    int nrows)
{
    const unsigned FULL = 0xffffffffu;
    int warp = (int)((blockIdx.x * blockDim.x + threadIdx.x) >> 5);
    int lane = threadIdx.x & 31;
    int grp  = lane >> 3;       // 0..3: which row in this warp
    int sub  = lane & 7;        // 0..7: lane within row group
    unsigned gmask = 0xFFu << (grp * 8);

    long row = (long)warp * 4 + grp;
    bool active = row < nrows;
    long ridx = active ? row : 0;

    int uid = user_ids[ridx];
    int it  = item_ids[ridx];
    int cc  = concept_ids[ridx];
    int nb  = nbmod[it];

    const float* ub = uemb + (size_t)uid * DC;
    const float* wb = W + (size_t)cc * DIN * DC;

    // ---- item-response vectors for this lane's two modalities (issue early) ----
    int m2 = sub + 8;
    const float* ebase = irw + (size_t)it * MM * DIN;
    float f0 = 0.f, f1 = 0.f, f2 = 0.f;   // e for m = sub
    float g0 = 0.f, g1 = 0.f, g2 = 0.f;   // e for m = sub+8
    {
        const float* e1p = ebase + sub * DIN;
        f0 = e1p[0]; f1 = e1p[1]; f2 = e1p[2];
        if (m2 < MM) {
            const float* e2p = ebase + m2 * DIN;
            g0 = e2p[0]; g1 = e2p[1]; g2 = e2p[2];
        }
    }
    const float4* Gp = reinterpret_cast<const float4*>(g_G + cc * 8);
    float4 Ga = __ldg(Gp);        // G00 G01 G02 G11
    float4 Gb = __ldg(Gp + 1);    // G12 G22 _ _

    // ---- dot products: 4 chunks x 4 channels per lane ----
    float v0 = 0.f, v1 = 0.f, v2 = 0.f;
    #pragma unroll
    for (int k = 0; k < 4; k++) {
        int off = k * 32 + sub * 4;
        float4 u4 = __ldcs(reinterpret_cast<const float4*>(ub + off));
        float4 a0 = *reinterpret_cast<const float4*>(wb + off);
        float4 a1 = *reinterpret_cast<const float4*>(wb + DC + off);
        float4 a2 = *reinterpret_cast<const float4*>(wb + 2 * DC + off);
        v0 += u4.x*a0.x + u4.y*a0.y + u4.z*a0.z + u4.w*a0.w;
        v1 += u4.x*a1.x + u4.y*a1.y + u4.z*a1.z + u4.w*a1.w;
        v2 += u4.x*a2.x + u4.y*a2.y + u4.z*a2.z + u4.w*a2.w;
    }

    // ---- 3-stage all-reduce within the 8-lane group ----
    #pragma unroll
    for (int off = 4; off; off >>= 1) {
        v0 += __shfl_xor_sync(FULL, v0, off);
        v1 += __shfl_xor_sync(FULL, v1, off);
        v2 += __shfl_xor_sync(FULL, v2, off);
    }

    // ---- score both modalities; keep smaller m on ties ----
    const float INF = __int_as_float(0x7f800000);
    bool valid1 = (sub >= 1) & (sub <= nb);       // m = sub  (sub<=7 < MM)
    bool valid2 = (m2 <= nb);                     // m = sub+8 (nb<=12 so m2<=12<MM)
    float best = INF;
    int   bm   = 15;
    if (valid2) {
        float q = g0*g0*Ga.x + g1*g1*Ga.w + g2*g2*Gb.y
                + 2.0f*(g0*g1*Ga.y + g0*g2*Ga.z + g1*g2*Gb.x);
        best = q - 2.0f*(g0*v0 + g1*v1 + g2*v2);
        bm = m2;
    }
    if (valid1) {
        float q = f0*f0*Ga.x + f1*f1*Ga.w + f2*f2*Gb.y
                + 2.0f*(f0*f1*Ga.y + f0*f2*Ga.z + f1*f2*Gb.x);
        float s = q - 2.0f*(f0*v0 + f1*v1 + f2*v2);
        if (s <= best) { best = s; bm = sub; }    // <=: smaller m wins ties
    }

    // ---- cross-lane argmin: orderable key, m in low 4 bits ----
    unsigned sb  = __float_as_uint(best);
    unsigned key = ((int)sb >= 0) ? (sb | 0x80000000u) : ~sb;
    unsigned packed = (key & 0xFFFFFFF0u) | (unsigned)bm;
    unsigned mnp = redux_min_u32(packed, gmask);
    int bi = (int)(mnp & 0xFu);

    if (sub == 0 && active) {
        out[row] = ((float)bi - 1.0f) / ((float)nb - 1.0f) + 1.0f;
    }
}

extern "C" void kernel_launch(void* const* d_in, const int* in_sizes, int n_in,
                              void* d_out, int out_size) {
    const int*   user_ids    = (const int*)  d_in[0];
    const int*   item_ids    = (const int*)  d_in[1];
    const int*   concept_ids = (const int*)  d_in[2];
    const float* uemb        = (const float*)d_in[3];
    const float* irw         = (const float*)d_in[4];
    const float* W           = (const float*)d_in[5];
    const float* maskt       = (const float*)d_in[6];
    const int*   nbmod       = (const int*)  d_in[7];
    float* out = (float*)d_out;
    int nrows = in_sizes[0];

    gmat_kernel<<<CONCEPTS, 32>>>(W);

    int warps = (nrows + 3) / 4;          // 4 rows per warp
    int blocks = (warps + 7) / 8;         // 256 threads = 8 warps
    impact_kernel<<<blocks, 256>>>(
        user_ids, item_ids, concept_ids, uemb, irw, W, maskt, nbmod, out, nrows);
}

// round 13
// speedup vs baseline: 1.0115x; 1.0115x over previous
#include <cuda_runtime.h>

#define CONCEPTS 128
#define MM 14          // nb_mod_max + 2
#define DC 128         // concept dim
#define DIN 3
#define ITEM_N 20000
#define ESLOTS 16      // padded modality slots per item (256B record)

// Per-concept Gram G = W[c] W[c]^T, padded to 8 floats: {G00,G01,G02,G11,G12,G22,_,_}
__device__ float  g_G[CONCEPTS * 8];
// Per-item packed record: slot m = (e0,e1,e2,pad); slot0.pad = (float)nb_modalities;
// slots 14,15 zero. 256B-aligned per item -> each half is exactly one 128B line.
__device__ float4 g_E[ITEM_N * ESLOTS];

__device__ __forceinline__ unsigned redux_min_u32(unsigned v, unsigned mask) {
    unsigned r;
    asm volatile("redux.sync.min.u32 %0, %1, %2;" : "=r"(r) : "r"(v), "r"(mask));
    return r;
}

// ---------------------------------------------------------------------------
// G[c] = W[c] W[c]^T. One warp per concept.
// ---------------------------------------------------------------------------
__global__ void gmat_kernel(const float* __restrict__ W) {
    int c = blockIdx.x;
    int lane = threadIdx.x;
    const float4* w = reinterpret_cast<const float4*>(W + (size_t)c * DIN * DC);
    float4 a = w[lane];
    float4 b = w[32 + lane];
    float4 d = w[64 + lane];
    float s[6];
    s[0] = a.x*a.x + a.y*a.y + a.z*a.z + a.w*a.w;
    s[1] = a.x*b.x + a.y*b.y + a.z*b.z + a.w*b.w;
    s[2] = a.x*d.x + a.y*d.y + a.z*d.z + a.w*d.w;
    s[3] = b.x*b.x + b.y*b.y + b.z*b.z + b.w*b.w;
    s[4] = b.x*d.x + b.y*d.y + b.z*d.z + b.w*d.w;
    s[5] = d.x*d.x + d.y*d.y + d.z*d.z + d.w*d.w;
    #pragma unroll
    for (int off = 16; off; off >>= 1)
        #pragma unroll
        for (int k = 0; k < 6; k++)
            s[k] += __shfl_xor_sync(0xffffffffu, s[k], off);
    if (lane == 0) {
        #pragma unroll
        for (int k = 0; k < 6; k++) g_G[c * 8 + k] = s[k];
        g_G[c * 8 + 6] = 0.0f;
        g_G[c * 8 + 7] = 0.0f;
    }
}

// ---------------------------------------------------------------------------
// Repack item-response table: g_E[item*16 + m] = (e0,e1,e2,pad).
// Reads of irw are fully coalesced (thread idx -> floats [3*idx, 3*idx+3)).
// ---------------------------------------------------------------------------
__global__ void repack_kernel(const float* __restrict__ irw,
                              const int*   __restrict__ nbmod) {
    int idx = blockIdx.x * blockDim.x + threadIdx.x;   // over ITEM_N * ESLOTS
    if (idx >= ITEM_N * ESLOTS) return;
    int item = idx >> 4;
    int m    = idx & 15;
    float4 z = make_float4(0.f, 0.f, 0.f, 0.f);
    if (m < MM) {
        const float* e = irw + ((size_t)item * MM + m) * DIN;
        z.x = e[0]; z.y = e[1]; z.z = e[2];
        if (m == 0) z.w = (float)nbmod[item];
    }
    g_E[idx] = z;
}

// ---------------------------------------------------------------------------
// 4 rows per warp; 8 lanes per row (grp = lane>>3, sub = lane&7).
// Per LDG.128: 4 rows x 128B contiguous = full lines (wavefront-optimal).
// Item side: 2 LDG.128 per lane from the packed g_E record (2 lines/item total),
// nb broadcast via one shfl from the sub==0 lane.
// ---------------------------------------------------------------------------
__global__ void __launch_bounds__(256) impact_kernel(
    const int*   __restrict__ user_ids,
    const int*   __restrict__ item_ids,
    const int*   __restrict__ concept_ids,
    const float* __restrict__ uemb,     // (USER_N, 128)
    const float* __restrict__ W,        // (128, 3, 128)
    float*       __restrict__ out,
    int nrows)
{
    const unsigned FULL = 0xffffffffu;
    int warp = (int)((blockIdx.x * blockDim.x + threadIdx.x) >> 5);
    int lane = threadIdx.x & 31;
    int sub  = lane & 7;        // 0..7: lane within row group
    int grp8 = lane & 24;       // grp*8: first lane of this row group
    unsigned gmask = 0xFFu << grp8;

    long row = (long)warp * 4 + (lane >> 3);
    bool active = row < nrows;
    long ridx = active ? row : 0;

    int uid = user_ids[ridx];
    int it  = item_ids[ridx];
    int cc  = concept_ids[ridx];

    const float* ub = uemb + (size_t)uid * DC;
    const float* wb = W + (size_t)cc * DIN * DC;

    // ---- packed item record: 2 vector loads, 2 lines per item ----
    int m2 = sub + 8;
    const float4* Eb = g_E + (size_t)it * ESLOTS;
    float4 E1 = __ldg(Eb + sub);       // m = sub   (slot0.w carries nb)
    float4 E2 = __ldg(Eb + m2);        // m = sub+8 (slots 14,15 are zero)
    float nbf = __shfl_sync(FULL, E1.w, grp8);   // broadcast nb within group
    int   nb  = (int)nbf;

    const float4* Gp = reinterpret_cast<const float4*>(g_G + cc * 8);
    float4 Ga = __ldg(Gp);        // G00 G01 G02 G11
    float4 Gb = __ldg(Gp + 1);    // G12 G22 _ _

    // ---- dot products: 4 chunks x 4 channels per lane ----
    float v0 = 0.f, v1 = 0.f, v2 = 0.f;
    #pragma unroll
    for (int k = 0; k < 4; k++) {
        int off = k * 32 + sub * 4;
        float4 u4 = __ldcs(reinterpret_cast<const float4*>(ub + off));
        float4 a0 = *reinterpret_cast<const float4*>(wb + off);
        float4 a1 = *reinterpret_cast<const float4*>(wb + DC + off);
        float4 a2 = *reinterpret_cast<const float4*>(wb + 2 * DC + off);
        v0 += u4.x*a0.x + u4.y*a0.y + u4.z*a0.z + u4.w*a0.w;
        v1 += u4.x*a1.x + u4.y*a1.y + u4.z*a1.z + u4.w*a1.w;
        v2 += u4.x*a2.x + u4.y*a2.y + u4.z*a2.z + u4.w*a2.w;
    }

    // ---- 3-stage all-reduce within the 8-lane group ----
    #pragma unroll
    for (int off = 4; off; off >>= 1) {
        v0 += __shfl_xor_sync(FULL, v0, off);
        v1 += __shfl_xor_sync(FULL, v1, off);
        v2 += __shfl_xor_sync(FULL, v2, off);
    }

    // ---- score both modalities; keep smaller m on ties ----
    const float INF = __int_as_float(0x7f800000);
    bool valid1 = (sub >= 1) & (sub <= nb);       // m = sub  (sub<=7 < MM)
    bool valid2 = (m2 <= nb);                     // nb<=12 so m2 in [8,12] only
    float best = INF;
    int   bm   = 15;
    if (valid2) {
        float q = E2.x*E2.x*Ga.x + E2.y*E2.y*Ga.w + E2.z*E2.z*Gb.y
                + 2.0f*(E2.x*E2.y*Ga.y + E2.x*E2.z*Ga.z + E2.y*E2.z*Gb.x);
        best = q - 2.0f*(E2.x*v0 + E2.y*v1 + E2.z*v2);
        bm = m2;
    }
    if (valid1) {
        float q = E1.x*E1.x*Ga.x + E1.y*E1.y*Ga.w + E1.z*E1.z*Gb.y
                + 2.0f*(E1.x*E1.y*Ga.y + E1.x*E1.z*Ga.z + E1.y*E1.z*Gb.x);
        float s = q - 2.0f*(E1.x*v0 + E1.y*v1 + E1.z*v2);
        if (s <= best) { best = s; bm = sub; }    // <=: smaller m wins ties
    }

    // ---- cross-lane argmin: orderable key, m in low 4 bits ----
    unsigned sb  = __float_as_uint(best);
    unsigned key = ((int)sb >= 0) ? (sb | 0x80000000u) : ~sb;
    unsigned packed = (key & 0xFFFFFFF0u) | (unsigned)bm;
    unsigned mnp = redux_min_u32(packed, gmask);
    int bi = (int)(mnp & 0xFu);

    if (sub == 0 && active) {
        out[row] = ((float)bi - 1.0f) / (nbf - 1.0f) + 1.0f;
    }
}

extern "C" void kernel_launch(void* const* d_in, const int* in_sizes, int n_in,
                              void* d_out, int out_size) {
    const int*   user_ids    = (const int*)  d_in[0];
    const int*   item_ids    = (const int*)  d_in[1];
    const int*   concept_ids = (const int*)  d_in[2];
    const float* uemb        = (const float*)d_in[3];
    const float* irw         = (const float*)d_in[4];
    const float* W           = (const float*)d_in[5];
    const int*   nbmod       = (const int*)  d_in[7];
    float* out = (float*)d_out;
    int nrows = in_sizes[0];

    gmat_kernel<<<CONCEPTS, 32>>>(W);
    repack_kernel<<<(ITEM_N * ESLOTS + 255) / 256, 256>>>(irw, nbmod);

    int warps = (nrows + 3) / 4;          // 4 rows per warp
    int blocks = (warps + 7) / 8;         // 256 threads = 8 warps
    impact_kernel<<<blocks, 256>>>(
        user_ids, item_ids, concept_ids, uemb, W, out, nrows);
}

// round 15
// speedup vs baseline: 1.0717x; 1.0595x over previous
#include <cuda_runtime.h>

#define CONCEPTS 128
#define MM 14          // nb_mod_max + 2
#define DC 128         // concept dim
#define DIN 3
#define ITEM_N 20000
#define ESLOTS 16      // padded modality slots per item (256B record)
#define REPACK_ELEMS (ITEM_N * ESLOTS)
#define GMAT_THREADS (CONCEPTS * 32)
#define PREP_THREADS (GMAT_THREADS + REPACK_ELEMS)

// Per-concept Gram G = W[c] W[c]^T, padded to 8 floats: {G00,G01,G02,G11,G12,G22,_,_}
__device__ float  g_G[CONCEPTS * 8];
// Per-item packed record: slot m = (e0,e1,e2,pad); slot0.pad = (float)nb_modalities;
// slots 14,15 zero. 256B-aligned per item -> each 8-slot half is one 128B line.
__device__ float4 g_E[ITEM_N * ESLOTS];

__device__ __forceinline__ unsigned redux_min_u32(unsigned v, unsigned mask) {
    unsigned r;
    asm volatile("redux.sync.min.u32 %0, %1, %2;" : "=r"(r) : "r"(v), "r"(mask));
    return r;
}

// ---------------------------------------------------------------------------
// Fused prologue: warps 0..127 compute G[c]; all later threads repack g_E.
// One launch at full parallelism (vs two tiny serialized launches).
// ---------------------------------------------------------------------------
__global__ void __launch_bounds__(256) prep_kernel(
    const float* __restrict__ W,
    const float* __restrict__ irw,
    const int*   __restrict__ nbmod)
{
    int gtid = blockIdx.x * blockDim.x + threadIdx.x;

    if (gtid < GMAT_THREADS) {
        // ---- Gram matrices: one warp per concept ----
        int c = gtid >> 5;
        int lane = gtid & 31;
        const float4* w = reinterpret_cast<const float4*>(W + (size_t)c * DIN * DC);
        float4 a = w[lane];
        float4 b = w[32 + lane];
        float4 d = w[64 + lane];
        float s[6];
        s[0] = a.x*a.x + a.y*a.y + a.z*a.z + a.w*a.w;
        s[1] = a.x*b.x + a.y*b.y + a.z*b.z + a.w*b.w;
        s[2] = a.x*d.x + a.y*d.y + a.z*d.z + a.w*d.w;
        s[3] = b.x*b.x + b.y*b.y + b.z*b.z + b.w*b.w;
        s[4] = b.x*d.x + b.y*d.y + b.z*d.z + b.w*d.w;
        s[5] = d.x*d.x + d.y*d.y + d.z*d.z + d.w*d.w;
        #pragma unroll
        for (int off = 16; off; off >>= 1)
            #pragma unroll
            for (int k = 0; k < 6; k++)
                s[k] += __shfl_xor_sync(0xffffffffu, s[k], off);
        if (lane == 0) {
            #pragma unroll
            for (int k = 0; k < 6; k++) g_G[c * 8 + k] = s[k];
            g_G[c * 8 + 6] = 0.0f;
            g_G[c * 8 + 7] = 0.0f;
        }
    } else {
        // ---- E-record repack ----
        int idx = gtid - GMAT_THREADS;
        if (idx < REPACK_ELEMS) {
            int item = idx >> 4;
            int m    = idx & 15;
            float4 z = make_float4(0.f, 0.f, 0.f, 0.f);
            if (m < MM) {
                const float* e = irw + ((size_t)item * MM + m) * DIN;
                z.x = e[0]; z.y = e[1]; z.z = e[2];
                if (m == 0) z.w = (float)nbmod[item];
            }
            g_E[idx] = z;
        }
    }
}

// ---------------------------------------------------------------------------
// 4 rows per warp; 8 lanes per row (grp = lane>>3, sub = lane&7).
// Per LDG.128: 4 rows x 128B contiguous = full lines (wavefront-optimal).
// Item side: 2 LDG.128 per lane from the packed g_E record (2 lines/item),
// nb broadcast via one shfl from the sub==0 lane.
// ---------------------------------------------------------------------------
__global__ void __launch_bounds__(256) impact_kernel(
    const int*   __restrict__ user_ids,
    const int*   __restrict__ item_ids,
    const int*   __restrict__ concept_ids,
    const float* __restrict__ uemb,     // (USER_N, 128)
    const float* __restrict__ W,        // (128, 3, 128)
    float*       __restrict__ out,
    int nrows)
{
    const unsigned FULL = 0xffffffffu;
    int warp = (int)((blockIdx.x * blockDim.x + threadIdx.x) >> 5);
    int lane = threadIdx.x & 31;
    int sub  = lane & 7;        // 0..7: lane within row group
    int grp8 = lane & 24;       // grp*8: first lane of this row group
    unsigned gmask = 0xFFu << grp8;

    long row = (long)warp * 4 + (lane >> 3);
    bool active = row < nrows;
    long ridx = active ? row : 0;

    int uid = user_ids[ridx];
    int it  = item_ids[ridx];
    int cc  = concept_ids[ridx];

    const float* ub = uemb + (size_t)uid * DC;
    const float* wb = W + (size_t)cc * DIN * DC;

    // ---- packed item record: 2 vector loads, 2 lines per item ----
    int m2 = sub + 8;
    const float4* Eb = g_E + (size_t)it * ESLOTS;
    float4 E1 = __ldg(Eb + sub);       // m = sub   (slot0.w carries nb)
    float4 E2 = __ldg(Eb + m2);        // m = sub+8 (slots 14,15 are zero)
    float nbf = __shfl_sync(FULL, E1.w, grp8);   // broadcast nb within group
    int   nb  = (int)nbf;

    const float4* Gp = reinterpret_cast<const float4*>(g_G + cc * 8);
    float4 Ga = __ldg(Gp);        // G00 G01 G02 G11
    float4 Gb = __ldg(Gp + 1);    // G12 G22 _ _

    // ---- dot products: 4 chunks x 4 channels per lane ----
    float v0 = 0.f, v1 = 0.f, v2 = 0.f;
    #pragma unroll
    for (int k = 0; k < 4; k++) {
        int off = k * 32 + sub * 4;
        float4 u4 = __ldcs(reinterpret_cast<const float4*>(ub + off));
        float4 a0 = *reinterpret_cast<const float4*>(wb + off);
        float4 a1 = *reinterpret_cast<const float4*>(wb + DC + off);
        float4 a2 = *reinterpret_cast<const float4*>(wb + 2 * DC + off);
        v0 += u4.x*a0.x + u4.y*a0.y + u4.z*a0.z + u4.w*a0.w;
        v1 += u4.x*a1.x + u4.y*a1.y + u4.z*a1.z + u4.w*a1.w;
        v2 += u4.x*a2.x + u4.y*a2.y + u4.z*a2.z + u4.w*a2.w;
    }

    // ---- 3-stage all-reduce within the 8-lane group ----
    #pragma unroll
    for (int off = 4; off; off >>= 1) {
        v0 += __shfl_xor_sync(FULL, v0, off);
        v1 += __shfl_xor_sync(FULL, v1, off);
        v2 += __shfl_xor_sync(FULL, v2, off);
    }

    // ---- score both modalities; keep smaller m on ties ----
    const float INF = __int_as_float(0x7f800000);
    bool valid1 = (sub >= 1) & (sub <= nb);       // m = sub  (sub<=7 < MM)
    bool valid2 = (m2 <= nb);                     // nb<=12 so m2 in [8,12] only
    float best = INF;
    int   bm   = 15;
    if (valid2) {
        float q = E2.x*E2.x*Ga.x + E2.y*E2.y*Ga.w + E2.z*E2.z*Gb.y
                + 2.0f*(E2.x*E2.y*Ga.y + E2.x*E2.z*Ga.z + E2.y*E2.z*Gb.x);
        best = q - 2.0f*(E2.x*v0 + E2.y*v1 + E2.z*v2);
        bm = m2;
    }
    if (valid1) {
        float q = E1.x*E1.x*Ga.x + E1.y*E1.y*Ga.w + E1.z*E1.z*Gb.y
                + 2.0f*(E1.x*E1.y*Ga.y + E1.x*E1.z*Ga.z + E1.y*E1.z*Gb.x);
        float s = q - 2.0f*(E1.x*v0 + E1.y*v1 + E1.z*v2);
        if (s <= best) { best = s; bm = sub; }    // <=: smaller m wins ties
    }

    // ---- cross-lane argmin: orderable key, m in low 4 bits ----
    unsigned sb  = __float_as_uint(best);
    unsigned key = ((int)sb >= 0) ? (sb | 0x80000000u) : ~sb;
    unsigned packed = (key & 0xFFFFFFF0u) | (unsigned)bm;
    unsigned mnp = redux_min_u32(packed, gmask);
    int bi = (int)(mnp & 0xFu);

    if (sub == 0 && active) {
        out[row] = ((float)bi - 1.0f) / (nbf - 1.0f) + 1.0f;
    }
}

extern "C" void kernel_launch(void* const* d_in, const int* in_sizes, int n_in,
                              void* d_out, int out_size) {
    const int*   user_ids    = (const int*)  d_in[0];
    const int*   item_ids    = (const int*)  d_in[1];
    const int*   concept_ids = (const int*)  d_in[2];
    const float* uemb        = (const float*)d_in[3];
    const float* irw         = (const float*)d_in[4];
    const float* W           = (const float*)d_in[5];
    const int*   nbmod       = (const int*)  d_in[7];
    float* out = (float*)d_out;
    int nrows = in_sizes[0];

    prep_kernel<<<(PREP_THREADS + 255) / 256, 256>>>(W, irw, nbmod);

    int warps = (nrows + 3) / 4;          // 4 rows per warp
    int blocks = (warps + 7) / 8;         // 256 threads = 8 warps
    impact_kernel<<<blocks, 256>>>(
        user_ids, item_ids, concept_ids, uemb, W, out, nrows);
}